// round 3
// baseline (speedup 1.0000x reference)
#include <cuda_runtime.h>
#include <math.h>
#include <float.h>

typedef unsigned long long u64;
typedef unsigned int u32;

static constexpr int NB = 8, N1 = 4096, N2 = 2048, N3 = 512, KNN = 32;

// ---------------- scratch ----------------
__device__ int   g_idx1[NB * N1 * KNN];
__device__ int   g_cnt1[NB * N1];
__device__ float g_x1  [NB * N1 * 64];
__device__ int   g_fi1 [NB * N2];
__device__ float g_pos2[NB * N2 * 3];
__device__ float g_x2g [NB * N2 * 64];
__device__ int   g_idx2[NB * N2 * KNN];
__device__ int   g_cnt2[NB * N2];
__device__ float g_x2  [NB * N2 * 128];
__device__ int   g_fi2 [NB * N3];
__device__ float g_pos3[NB * N3 * 3];
__device__ float g_x3g [NB * N3 * 128];
__device__ int   g_idx3[NB * N3 * KNN];
__device__ int   g_cnt3[NB * N3];
__device__ float g_x3  [NB * N3 * 256];

// ---------------- f32x2 helpers ----------------
__device__ __forceinline__ u64 fma2(u64 a, u64 b, u64 c) {
    u64 d; asm("fma.rn.f32x2 %0,%1,%2,%3;" : "=l"(d) : "l"(a), "l"(b), "l"(c));
    return d;
}
__device__ __forceinline__ u64 pack2(float x, float y) {
    u64 d; asm("mov.b64 %0,{%1,%2};" : "=l"(d) : "f"(x), "f"(y)); return d;
}
__device__ __forceinline__ float2 unpack2(u64 v) {
    float2 r; asm("mov.b64 {%0,%1},%2;" : "=f"(r.x), "=f"(r.y) : "l"(v)); return r;
}
// order-preserving float->u32 key (handles tiny negatives safely)
__device__ __forceinline__ u32 fkey(float f) {
    u32 b = __float_as_uint(f);
    return (b & 0x80000000u) ? ~b : (b | 0x80000000u);
}

// ---------------- KNN device routine (512 threads/block) ----------------
// top-32 by d2 among points with d2<=r2, sorted; packed u64 gives
// lowest-index-first tie-break exactly like lax.top_k.
__device__ void knn_dev(const float* __restrict__ pb, int N, float r2v,
                        int* __restrict__ oidx, int* __restrict__ ocnt,
                        int qb, float4* sj)
{
    const int t = threadIdx.x;
    const int i = qb * 512 + t;
    const float xi = pb[i * 3 + 0], yi = pb[i * 3 + 1], zi = pb[i * 3 + 2];
    const float sqi = __fadd_rn(__fadd_rn(__fmul_rn(xi, xi), __fmul_rn(yi, yi)),
                                __fmul_rn(zi, zi));
    const float m2x = -2.f * xi, m2y = -2.f * yi, m2z = -2.f * zi;

    u64 bb[KNN];
#pragma unroll
    for (int k = 0; k < KNN; ++k) bb[k] = ~0ull;
    u64 worst = ~0ull;

    for (int t0 = 0; t0 < N; t0 += 512) {
        __syncthreads();
        {
            int j = t0 + t;
            float x = pb[j * 3 + 0], y = pb[j * 3 + 1], z = pb[j * 3 + 2];
            float sq = __fadd_rn(__fadd_rn(__fmul_rn(x, x), __fmul_rn(y, y)),
                                 __fmul_rn(z, z));
            sj[t] = make_float4(x, y, z, sq);
        }
        __syncthreads();
#pragma unroll 4
        for (int jj = 0; jj < 512; ++jj) {
            float4 q = sj[jj];
            float d2 = sqi + fmaf(m2x, q.x, fmaf(m2y, q.y, fmaf(m2z, q.z, q.w)));
            int j = t0 + jj;
            if (d2 <= r2v && j != i) {
                u64 key = ((u64)fkey(d2) << 32) | (u32)j;
                if (key < worst) {
                    int p = KNN - 1;
                    while (p > 0 && bb[p - 1] > key) { bb[p] = bb[p - 1]; --p; }
                    bb[p] = key;
                    worst = bb[KNN - 1];
                }
            }
        }
    }
    int cnt = 0;
    while (cnt < KNN && bb[cnt] != ~0ull) ++cnt;
    ocnt[i] = cnt;
    const int base = i * KNN;
#pragma unroll
    for (int k = 0; k < KNN; ++k) oidx[base + k] = (int)(bb[k] & 0xffffffffu);
}

// ---------------- FPS device routine (512 threads/block) ----------------
template <int P>
__device__ void fps_dev(const float* __restrict__ pb, int nS,
                        int* __restrict__ out, float* sm)
{
    const int N = P * 512;
    float* spos = sm;
    u32*  svb = (u32*)(sm + N * 3);
    int*  si  = (int*)(svb + 16);
    __shared__ int sgi;
    const int t = threadIdx.x;

    for (int e = t; e < N * 3; e += 512) spos[e] = pb[e];
    __syncthreads();

    float px[P], py[P], pz[P], mind[P];
    const float x0 = spos[0], y0 = spos[1], z0 = spos[2];
    float bv = -1.f; int bidx = 0x7fffffff;
#pragma unroll
    for (int p = 0; p < P; ++p) {
        int i = t + p * 512;
        px[p] = spos[i * 3 + 0]; py[p] = spos[i * 3 + 1]; pz[p] = spos[i * 3 + 2];
        float dx = px[p] - x0, dy = py[p] - y0, dz = pz[p] - z0;
        mind[p] = __fadd_rn(__fadd_rn(__fmul_rn(dx, dx), __fmul_rn(dy, dy)),
                            __fmul_rn(dz, dz));
        if (mind[p] > bv) { bv = mind[p]; bidx = i; }
    }
    if (t == 0) out[0] = 0;

    for (int s = 1; s < nS; ++s) {
        u32 vb = __float_as_uint(bv);                    // mind>=0 -> monotone bits
        u32 m  = __reduce_max_sync(0xffffffffu, vb);
        u32 cand = (vb == m) ? (u32)bidx : 0xffffffffu;
        u32 wi = __reduce_min_sync(0xffffffffu, cand);
        if ((t & 31) == 0) { svb[t >> 5] = m; si[t >> 5] = (int)wi; }
        __syncthreads();
        if (t < 32) {
            u32 v2 = (t < 16) ? svb[t] : 0u;
            u32 i2 = (t < 16) ? (u32)si[t] : 0xffffffffu;
            u32 m2 = __reduce_max_sync(0xffffffffu, v2);
            u32 c2 = (v2 == m2 && t < 16) ? i2 : 0xffffffffu;
            u32 gi = __reduce_min_sync(0xffffffffu, c2);
            if (t == 0) { sgi = (int)gi; out[s] = (int)gi; }
        }
        __syncthreads();
        const int gi = sgi;
        const float cx = spos[gi * 3 + 0], cy = spos[gi * 3 + 1], cz = spos[gi * 3 + 2];
        bv = -1.f; bidx = 0x7fffffff;
#pragma unroll
        for (int p = 0; p < P; ++p) {
            float dx = px[p] - cx, dy = py[p] - cy, dz = pz[p] - cz;
            float d = __fadd_rn(__fadd_rn(__fmul_rn(dx, dx), __fmul_rn(dy, dy)),
                                __fmul_rn(dz, dz));
            mind[p] = fminf(mind[p], d);
            if (mind[p] > bv) { bv = mind[p]; bidx = t + p * 512; }
        }
    }
}

// ---------------- fused KNN + FPS launch (overlap on the grid) ----------
template <int P>
__global__ void __launch_bounds__(512)
mega_kernel(const float* __restrict__ pos, float r2v,
            int* __restrict__ oidx, int* __restrict__ ocnt,
            int nS, int* __restrict__ fi)
{
    extern __shared__ char sm[];
    const int N = P * 512;
    if (blockIdx.x < NB) {
        fps_dev<P>(pos + (size_t)blockIdx.x * N * 3, nS,
                   fi + blockIdx.x * nS, (float*)sm);
    } else {
        int kb = blockIdx.x - NB;
        int b = kb % NB, qb = kb / NB;
        knn_dev(pos + (size_t)b * N * 3, N, r2v,
                oidx + (size_t)b * N * KNN, ocnt + b * N, qb, (float4*)sm);
    }
}

__global__ void __launch_bounds__(512)
knn_kernel(const float* __restrict__ pos, int N, float r2v,
           int* __restrict__ oidx, int* __restrict__ ocnt)
{
    extern __shared__ char sm[];
    int b = blockIdx.x % NB, qb = blockIdx.x / NB;
    knn_dev(pos + (size_t)b * N * 3, N, r2v,
            oidx + (size_t)b * N * KNN, ocnt + b * N, qb, (float4*)sm);
}

// ---------------- gather after FPS ----------------
__global__ void gather_kernel(const float* __restrict__ xin,
                              const float* __restrict__ posin,
                              const int* __restrict__ fi,
                              float* __restrict__ xo, float* __restrict__ poso,
                              int Nin, int Nout, int C)
{
    const int tid = blockIdx.x * blockDim.x + threadIdx.x;
    const int stride = gridDim.x * blockDim.x;
    const int totX = NB * Nout * C;
    for (int e = tid; e < totX; e += stride) {
        int c = e % C, m = (e / C) % Nout, b = e / (C * Nout);
        int j = fi[b * Nout + m];
        xo[e] = xin[((size_t)b * Nin + j) * C + c];
    }
    const int totP = NB * Nout * 3;
    for (int e = tid; e < totP; e += stride) {
        int d = e % 3, m = (e / 3) % Nout, b = e / (3 * Nout);
        int j = fi[b * Nout + m];
        poso[e] = posin[((size_t)b * Nin + j) * 3 + d];
    }
}

// ---------------- PointNetConv with f32x2 packed FMA ----------------
// block = COUT threads, one point per block; vectorize over output-channel
// pairs so W float4 loads reinterpret directly as 2x u64 operands.
template <int CINX, int CHID, int COUT>
__global__ void __launch_bounds__(COUT)
conv_kernel(const float* __restrict__ xin, const float* __restrict__ pos,
            const int* __restrict__ kidx, const int* __restrict__ kcnt,
            const float* __restrict__ W1, const float* __restrict__ b1,
            const float* __restrict__ W2, const float* __restrict__ b2,
            float* __restrict__ xout, int N)
{
    constexpr int CINF = CINX + 3;
    extern __shared__ float smem[];
    float* sfeat = smem;               // [32][CINF]
    float* sh1   = smem + 32 * CINF;   // [32][CHID]
    __shared__ int   sidx[KNN];
    __shared__ float spi[3];
    __shared__ int   scnt;

    const int b = blockIdx.y, i = blockIdx.x, t = threadIdx.x;

    if (t < KNN) sidx[t] = kidx[((size_t)b * N + i) * KNN + t];
    if (t == 0)  scnt = kcnt[b * N + i];
    if (t < 3)   spi[t] = pos[((size_t)b * N + i) * 3 + t];
    for (int e = t; e < 32 * CINF; e += COUT) sfeat[e] = 0.f;
    __syncthreads();
    const int cnt = scnt;

    for (int e = t; e < cnt * CINF; e += COUT) {
        int k = e / CINF, f = e - k * CINF;
        int j = sidx[k];
        float v;
        if (f < CINX) v = xin[((size_t)b * N + j) * CINX + f];
        else          v = pos[((size_t)b * N + j) * 3 + (f - CINX)] - spi[f - CINX];
        sfeat[k * CINF + f] = v;
    }
    __syncthreads();

    // phase 1: h1 = relu(feats @ W1 + b1)
    {
        constexpr int CG = CHID / 4;
        const int c0 = (t % CG) * 4;
        const int k0 = (t / CG) * 8;
        u64 a[2][8];
        float4 bb4 = *(const float4*)&b1[c0];
        const u64 i0 = pack2(bb4.x, bb4.y), i1 = pack2(bb4.z, bb4.w);
#pragma unroll
        for (int k = 0; k < 8; ++k) { a[0][k] = i0; a[1][k] = i1; }
#pragma unroll 2
        for (int f = 0; f < CINF; ++f) {
            ulonglong2 wv = __ldg((const ulonglong2*)&W1[f * CHID + c0]);
#pragma unroll
            for (int k = 0; k < 8; ++k) {
                float s = sfeat[(k0 + k) * CINF + f];
                u64 sp = pack2(s, s);
                a[0][k] = fma2(sp, wv.x, a[0][k]);
                a[1][k] = fma2(sp, wv.y, a[1][k]);
            }
        }
#pragma unroll
        for (int k = 0; k < 8; ++k) {
            float2 v0 = unpack2(a[0][k]), v1 = unpack2(a[1][k]);
            float4 o;
            o.x = fmaxf(v0.x, 0.f); o.y = fmaxf(v0.y, 0.f);
            o.z = fmaxf(v1.x, 0.f); o.w = fmaxf(v1.y, 0.f);
            *(float4*)&sh1[(k0 + k) * CHID + c0] = o;
        }
    }
    __syncthreads();

    // phase 2: acc = h1 @ W2, masked max over valid neighbors
    float mv[4] = { -FLT_MAX, -FLT_MAX, -FLT_MAX, -FLT_MAX };
    int o0, kg;
    {
        constexpr int OG = COUT / 4;
        o0 = (t % OG) * 4;
        kg = t / OG;
        const int k0 = kg * 8;
        u64 a[2][8];
#pragma unroll
        for (int k = 0; k < 8; ++k) { a[0][k] = 0ull; a[1][k] = 0ull; }
#pragma unroll 2
        for (int cc = 0; cc < CHID; ++cc) {
            ulonglong2 wv = __ldg((const ulonglong2*)&W2[cc * COUT + o0]);
#pragma unroll
            for (int k = 0; k < 8; ++k) {
                float s = sh1[(k0 + k) * CHID + cc];
                u64 sp = pack2(s, s);
                a[0][k] = fma2(sp, wv.x, a[0][k]);
                a[1][k] = fma2(sp, wv.y, a[1][k]);
            }
        }
#pragma unroll
        for (int k = 0; k < 8; ++k) {
            if (k0 + k < cnt) {
                float2 v0 = unpack2(a[0][k]), v1 = unpack2(a[1][k]);
                mv[0] = fmaxf(mv[0], v0.x); mv[1] = fmaxf(mv[1], v0.y);
                mv[2] = fmaxf(mv[2], v1.x); mv[3] = fmaxf(mv[3], v1.y);
            }
        }
    }
    __syncthreads();
    float* red = sh1;
    red[kg * COUT + o0 + 0] = mv[0];
    red[kg * COUT + o0 + 1] = mv[1];
    red[kg * COUT + o0 + 2] = mv[2];
    red[kg * COUT + o0 + 3] = mv[3];
    __syncthreads();
    float m = fmaxf(fmaxf(red[t], red[COUT + t]),
                    fmaxf(red[2 * COUT + t], red[3 * COUT + t]));
    float r = (cnt > 0) ? fmaxf(m + b2[t], 0.f) : 0.f;
    xout[((size_t)b * N + i) * COUT + t] = r;
}

// ---------------- head ----------------
__global__ void head_kernel(const float* __restrict__ x3,
                            const float* __restrict__ Wc1, const float* __restrict__ bc1,
                            const float* __restrict__ Wc2, const float* __restrict__ bc2,
                            const float* __restrict__ Wc3, const float* __restrict__ bc3,
                            const float* __restrict__ Wd1, const float* __restrict__ bd1,
                            const float* __restrict__ Wd2, const float* __restrict__ bd2,
                            float* __restrict__ out)
{
    __shared__ float sf[256], sh[256], sh2[256], slog[40], sd[2];
    const int b = blockIdx.x, t = threadIdx.x;

    float m = -FLT_MAX;
    for (int n = 0; n < N3; ++n)
        m = fmaxf(m, x3[((size_t)b * N3 + n) * 256 + t]);
    sf[t] = m;
    __syncthreads();

    float a = bc1[t];
    for (int c = 0; c < 256; ++c) a = fmaf(sf[c], Wc1[c * 256 + t], a);
    sh[t] = fmaxf(a, 0.f);
    __syncthreads();

    a = bc2[t];
    for (int c = 0; c < 256; ++c) a = fmaf(sh[c], Wc2[c * 256 + t], a);
    sh2[t] = fmaxf(a, 0.f);
    __syncthreads();

    if (t < 40) {
        float l = bc3[t];
        for (int c = 0; c < 256; ++c) l = fmaf(sh2[c], Wc3[c * 40 + t], l);
        slog[t] = l;
    }
    float a2 = bd1[t];
    for (int c = 0; c < 256; ++c) a2 = fmaf(sf[c], Wd1[c * 256 + t], a2);
    a2 = fmaxf(a2, 0.f);
    __syncthreads();
    sh[t] = a2;
    __syncthreads();
    if (t < 2) {
        float l = bd2[t];
        for (int c = 0; c < 256; ++c) l = fmaf(sh[c], Wd2[c * 2 + t], l);
        sd[t] = l;
    }
    __syncthreads();

    if (t < 40) {
        float mx = -FLT_MAX;
        for (int j = 0; j < 40; ++j) mx = fmaxf(mx, slog[j]);
        float se = 0.f;
        for (int j = 0; j < 40; ++j) se += expf(slog[j] - mx);
        out[b * 40 + t] = slog[t] - mx - logf(se);
    }
    if (t < 2) {
        float mx = fmaxf(sd[0], sd[1]);
        float se = expf(sd[0] - mx) + expf(sd[1] - mx);
        out[NB * 40 + b * 2 + t] = sd[t] - mx - logf(se);
    }
}

// ---------------- launch ----------------
extern "C" void kernel_launch(void* const* d_in, const int* in_sizes, int n_in,
                              void* d_out, int out_size)
{
    const float* pos = (const float*)d_in[0];
    const float* W1a = (const float*)d_in[1];  const float* b1a = (const float*)d_in[2];
    const float* W1b = (const float*)d_in[3];  const float* b1b = (const float*)d_in[4];
    const float* W2a = (const float*)d_in[5];  const float* b2a = (const float*)d_in[6];
    const float* W2b = (const float*)d_in[7];  const float* b2b = (const float*)d_in[8];
    const float* W3a = (const float*)d_in[9];  const float* b3a = (const float*)d_in[10];
    const float* W3b = (const float*)d_in[11]; const float* b3b = (const float*)d_in[12];
    const float* Wc1 = (const float*)d_in[13]; const float* bc1 = (const float*)d_in[14];
    const float* Wc2 = (const float*)d_in[15]; const float* bc2 = (const float*)d_in[16];
    const float* Wc3 = (const float*)d_in[17]; const float* bc3 = (const float*)d_in[18];
    const float* Wd1 = (const float*)d_in[19]; const float* bd1 = (const float*)d_in[20];
    const float* Wd2 = (const float*)d_in[21]; const float* bd2 = (const float*)d_in[22];
    float* out = (float*)d_out;

    void *p_idx1, *p_cnt1, *p_x1, *p_fi1, *p_pos2, *p_x2g, *p_idx2, *p_cnt2,
         *p_x2, *p_fi2, *p_pos3, *p_x3g, *p_idx3, *p_cnt3, *p_x3;
    cudaGetSymbolAddress(&p_idx1, g_idx1);
    cudaGetSymbolAddress(&p_cnt1, g_cnt1);
    cudaGetSymbolAddress(&p_x1,   g_x1);
    cudaGetSymbolAddress(&p_fi1,  g_fi1);
    cudaGetSymbolAddress(&p_pos2, g_pos2);
    cudaGetSymbolAddress(&p_x2g,  g_x2g);
    cudaGetSymbolAddress(&p_idx2, g_idx2);
    cudaGetSymbolAddress(&p_cnt2, g_cnt2);
    cudaGetSymbolAddress(&p_x2,   g_x2);
    cudaGetSymbolAddress(&p_fi2,  g_fi2);
    cudaGetSymbolAddress(&p_pos3, g_pos3);
    cudaGetSymbolAddress(&p_x3g,  g_x3g);
    cudaGetSymbolAddress(&p_idx3, g_idx3);
    cudaGetSymbolAddress(&p_cnt3, g_cnt3);
    cudaGetSymbolAddress(&p_x3,   g_x3);

    const int smMega1 = N1 * 12 + 128;                     // 49280
    const int smMega2 = N2 * 12 + 128;                     // 24704
    const int smKnn3  = 512 * 16;                          // 8192
    const int sh1b = (32 * 3   + 32 * 64)  * 4;
    const int sh2b = (32 * 67  + 32 * 128) * 4;
    const int sh3b = (32 * 131 + 32 * 256) * 4;            // 49536
    cudaFuncSetAttribute(mega_kernel<8>,
                         cudaFuncAttributeMaxDynamicSharedMemorySize, 50176);
    cudaFuncSetAttribute(conv_kernel<128, 256, 256>,
                         cudaFuncAttributeMaxDynamicSharedMemorySize, 50176);

    const float r1 = 0.2f, r2 = 0.4f, r3 = 1.0f;

    // level 1: knn1 + fps1 fused on one grid (both read pos)
    mega_kernel<8><<<NB + (N1 / 512) * NB, 512, smMega1>>>(
        pos, r1 * r1, (int*)p_idx1, (int*)p_cnt1, N2, (int*)p_fi1);
    conv_kernel<0, 64, 64><<<dim3(N1, NB), 64, sh1b>>>(
        nullptr, pos, (int*)p_idx1, (int*)p_cnt1,
        W1a, b1a, W1b, b1b, (float*)p_x1, N1);
    gather_kernel<<<256, 256>>>((float*)p_x1, pos, (int*)p_fi1,
                                (float*)p_x2g, (float*)p_pos2, N1, N2, 64);

    // level 2: knn2 + fps2 fused
    mega_kernel<4><<<NB + (N2 / 512) * NB, 512, smMega2>>>(
        (float*)p_pos2, r2 * r2, (int*)p_idx2, (int*)p_cnt2, N3, (int*)p_fi2);
    conv_kernel<64, 128, 128><<<dim3(N2, NB), 128, sh2b>>>(
        (float*)p_x2g, (float*)p_pos2, (int*)p_idx2, (int*)p_cnt2,
        W2a, b2a, W2b, b2b, (float*)p_x2, N2);
    gather_kernel<<<256, 256>>>((float*)p_x2, (float*)p_pos2, (int*)p_fi2,
                                (float*)p_x3g, (float*)p_pos3, N2, N3, 128);

    // level 3
    knn_kernel<<<(N3 / 512) * NB, 512, smKnn3>>>(
        (float*)p_pos3, N3, r3 * r3, (int*)p_idx3, (int*)p_cnt3);
    conv_kernel<128, 256, 256><<<dim3(N3, NB), 256, sh3b>>>(
        (float*)p_x3g, (float*)p_pos3, (int*)p_idx3, (int*)p_cnt3,
        W3a, b3a, W3b, b3b, (float*)p_x3, N3);

    // head
    head_kernel<<<NB, 256>>>((float*)p_x3, Wc1, bc1, Wc2, bc2, Wc3, bc3,
                             Wd1, bd1, Wd2, bd2, out);

    (void)in_sizes; (void)n_in; (void)out_size;
}

// round 4
// speedup vs baseline: 1.8335x; 1.8335x over previous
#include <cuda_runtime.h>
#include <math.h>
#include <float.h>

typedef unsigned int u32;

static constexpr int NB = 8, N1 = 4096, N2 = 2048, N3 = 512, KNN = 32;

// ---------------- scratch ----------------
__device__ int   g_idx1[NB * N1 * KNN];
__device__ int   g_cnt1[NB * N1];
__device__ float g_x1  [NB * N1 * 64];
__device__ int   g_fi1 [NB * N2];
__device__ float g_pos2[NB * N2 * 3];
__device__ float g_x2g [NB * N2 * 64];
__device__ int   g_idx2[NB * N2 * KNN];
__device__ int   g_cnt2[NB * N2];
__device__ float g_x2  [NB * N2 * 128];
__device__ int   g_fi2 [NB * N3];
__device__ float g_pos3[NB * N3 * 3];
__device__ float g_x3g [NB * N3 * 128];
__device__ int   g_idx3[NB * N3 * KNN];
__device__ int   g_cnt3[NB * N3];
__device__ float g_x3  [NB * N3 * 256];

// ---------------- KNN device routine (256 threads/block) ----------------
// Per-thread sorted top-32 among candidates with d2<=r2 (radius-gated to
// avoid warm-up insertions). Strict '<' ordering + stable shift keeps the
// lowest index first among ties, matching lax.top_k.
__device__ void knn_dev(const float* __restrict__ pb, int N, float r2v,
                        int* __restrict__ oidx, int* __restrict__ ocnt,
                        int qb, float4* sj)
{
    const int t = threadIdx.x;
    const int i = qb * 256 + t;
    const float xi = pb[i * 3 + 0], yi = pb[i * 3 + 1], zi = pb[i * 3 + 2];
    const float sqi = __fadd_rn(__fadd_rn(__fmul_rn(xi, xi), __fmul_rn(yi, yi)),
                                __fmul_rn(zi, zi));
    const float m2x = -2.f * xi, m2y = -2.f * yi, m2z = -2.f * zi;

    float bd[KNN];
    int   bi_[KNN];
#pragma unroll
    for (int k = 0; k < KNN; ++k) { bd[k] = FLT_MAX; bi_[k] = 0; }
    float worst = FLT_MAX;

    for (int t0 = 0; t0 < N; t0 += 256) {
        __syncthreads();
        {
            int j = t0 + t;
            float x = pb[j * 3 + 0], y = pb[j * 3 + 1], z = pb[j * 3 + 2];
            float sq = __fadd_rn(__fadd_rn(__fmul_rn(x, x), __fmul_rn(y, y)),
                                 __fmul_rn(z, z));
            sj[t] = make_float4(x, y, z, sq);
        }
        __syncthreads();
#pragma unroll 4
        for (int jj = 0; jj < 256; ++jj) {
            float4 q = sj[jj];
            float d2 = sqi + fmaf(m2x, q.x, fmaf(m2y, q.y, fmaf(m2z, q.z, q.w)));
            int j = t0 + jj;
            if (d2 <= r2v && d2 < worst && j != i) {
                int p = KNN - 1;
                while (p > 0 && bd[p - 1] > d2) {
                    bd[p] = bd[p - 1]; bi_[p] = bi_[p - 1]; --p;
                }
                bd[p] = d2; bi_[p] = j;
                worst = bd[KNN - 1];
            }
        }
    }
    int cnt = 0;
    while (cnt < KNN && bd[cnt] <= r2v) ++cnt;
    ocnt[i] = cnt;
    const int base = i * KNN;
#pragma unroll
    for (int k = 0; k < KNN; ++k) oidx[base + k] = bi_[k];
}

// ---------------- FPS device routine (256 threads/block) ----------------
template <int P>
__device__ void fps_dev(const float* __restrict__ pb, int nS,
                        int* __restrict__ out, float* sm)
{
    const int N = P * 256;
    float* spos = sm;
    u32*  svb = (u32*)(sm + N * 3);
    int*  si  = (int*)(svb + 8);
    __shared__ int sgi;
    const int t = threadIdx.x;

    for (int e = t; e < N * 3; e += 256) spos[e] = pb[e];
    __syncthreads();

    float px[P], py[P], pz[P], mind[P];
    const float x0 = spos[0], y0 = spos[1], z0 = spos[2];
    float bv = -1.f; int bidx = 0x7fffffff;
#pragma unroll
    for (int p = 0; p < P; ++p) {
        int i = t + p * 256;
        px[p] = spos[i * 3 + 0]; py[p] = spos[i * 3 + 1]; pz[p] = spos[i * 3 + 2];
        float dx = px[p] - x0, dy = py[p] - y0, dz = pz[p] - z0;
        mind[p] = __fadd_rn(__fadd_rn(__fmul_rn(dx, dx), __fmul_rn(dy, dy)),
                            __fmul_rn(dz, dz));
        if (mind[p] > bv) { bv = mind[p]; bidx = i; }
    }
    if (t == 0) out[0] = 0;

    for (int s = 1; s < nS; ++s) {
        u32 vb = __float_as_uint(bv);                 // mind >= 0 -> monotone
        u32 m  = __reduce_max_sync(0xffffffffu, vb);
        u32 cand = (vb == m) ? (u32)bidx : 0xffffffffu;
        u32 wi = __reduce_min_sync(0xffffffffu, cand);
        if ((t & 31) == 0) { svb[t >> 5] = m; si[t >> 5] = (int)wi; }
        __syncthreads();
        if (t < 32) {
            u32 v2 = (t < 8) ? svb[t] : 0u;
            u32 i2 = (t < 8) ? (u32)si[t] : 0xffffffffu;
            u32 m2 = __reduce_max_sync(0xffffffffu, v2);
            u32 c2 = (v2 == m2 && t < 8) ? i2 : 0xffffffffu;
            u32 gi = __reduce_min_sync(0xffffffffu, c2);
            if (t == 0) { sgi = (int)gi; out[s] = (int)gi; }
        }
        __syncthreads();
        const int gi = sgi;
        const float cx = spos[gi * 3 + 0], cy = spos[gi * 3 + 1], cz = spos[gi * 3 + 2];
        bv = -1.f; bidx = 0x7fffffff;
#pragma unroll
        for (int p = 0; p < P; ++p) {
            float dx = px[p] - cx, dy = py[p] - cy, dz = pz[p] - cz;
            float d = __fadd_rn(__fadd_rn(__fmul_rn(dx, dx), __fmul_rn(dy, dy)),
                                __fmul_rn(dz, dz));
            mind[p] = fminf(mind[p], d);
            if (mind[p] > bv) { bv = mind[p]; bidx = t + p * 256; }
        }
    }
}

// ---------------- fused KNN + FPS launch (overlap on the grid) ----------
template <int P>
__global__ void __launch_bounds__(256)
mega_kernel(const float* __restrict__ pos, float r2v,
            int* __restrict__ oidx, int* __restrict__ ocnt,
            int nS, int* __restrict__ fi)
{
    extern __shared__ char sm[];
    const int N = P * 256;
    if (blockIdx.x < NB) {
        fps_dev<P>(pos + (size_t)blockIdx.x * N * 3, nS,
                   fi + blockIdx.x * nS, (float*)sm);
    } else {
        int kb = blockIdx.x - NB;
        int b = kb % NB, qb = kb / NB;
        knn_dev(pos + (size_t)b * N * 3, N, r2v,
                oidx + (size_t)b * N * KNN, ocnt + b * N, qb, (float4*)sm);
    }
}

__global__ void __launch_bounds__(256)
knn_kernel(const float* __restrict__ pos, int N, float r2v,
           int* __restrict__ oidx, int* __restrict__ ocnt)
{
    extern __shared__ char sm[];
    int b = blockIdx.x % NB, qb = blockIdx.x / NB;
    knn_dev(pos + (size_t)b * N * 3, N, r2v,
            oidx + (size_t)b * N * KNN, ocnt + b * N, qb, (float4*)sm);
}

// ---------------- gather after FPS ----------------
__global__ void gather_kernel(const float* __restrict__ xin,
                              const float* __restrict__ posin,
                              const int* __restrict__ fi,
                              float* __restrict__ xo, float* __restrict__ poso,
                              int Nin, int Nout, int C)
{
    const int tid = blockIdx.x * blockDim.x + threadIdx.x;
    const int stride = gridDim.x * blockDim.x;
    const int totX = NB * Nout * C;
    for (int e = tid; e < totX; e += stride) {
        int c = e % C, m = (e / C) % Nout, b = e / (C * Nout);
        int j = fi[b * Nout + m];
        xo[e] = xin[((size_t)b * Nin + j) * C + c];
    }
    const int totP = NB * Nout * 3;
    for (int e = tid; e < totP; e += stride) {
        int d = e % 3, m = (e / 3) % Nout, b = e / (3 * Nout);
        int j = fi[b * Nout + m];
        poso[e] = posin[((size_t)b * Nin + j) * 3 + d];
    }
}

// ---------------- PointNetConv: scalar FFMA, 8-col x 4-k register tile ----
template <int CINX, int CHID, int COUT>
__global__ void __launch_bounds__(COUT)
conv_kernel(const float* __restrict__ xin, const float* __restrict__ pos,
            const int* __restrict__ kidx, const int* __restrict__ kcnt,
            const float* __restrict__ W1, const float* __restrict__ b1,
            const float* __restrict__ W2, const float* __restrict__ b2,
            float* __restrict__ xout, int N)
{
    constexpr int CINF = CINX + 3;
    extern __shared__ float smem[];
    float* sfeat = smem;               // [32][CINF]
    float* sh1   = smem + 32 * CINF;   // [32][CHID]
    __shared__ int   sidx[KNN];
    __shared__ float spi[3];
    __shared__ int   scnt;

    const int b = blockIdx.y, i = blockIdx.x, t = threadIdx.x;

    if (t < KNN) sidx[t] = kidx[((size_t)b * N + i) * KNN + t];
    if (t == 0)  scnt = kcnt[b * N + i];
    if (t < 3)   spi[t] = pos[((size_t)b * N + i) * 3 + t];
    for (int e = t; e < 32 * CINF; e += COUT) sfeat[e] = 0.f;
    __syncthreads();
    const int cnt = scnt;

    for (int e = t; e < cnt * CINF; e += COUT) {
        int k = e / CINF, f = e - k * CINF;
        int j = sidx[k];
        float v;
        if (f < CINX) v = xin[((size_t)b * N + j) * CINX + f];
        else          v = pos[((size_t)b * N + j) * 3 + (f - CINX)] - spi[f - CINX];
        sfeat[e] = v;
    }
    __syncthreads();

    // phase 1: h1 = relu(feats @ W1 + b1)   [32 x CINF] @ [CINF x CHID]
    {
        constexpr int CG = CHID / 8;
        const int c0 = (t % CG) * 8;
        const int k0 = (t / CG) * 4;
        float h[8][4];
        float4 ba = *(const float4*)&b1[c0];
        float4 bb = *(const float4*)&b1[c0 + 4];
#pragma unroll
        for (int k = 0; k < 4; ++k) {
            h[0][k] = ba.x; h[1][k] = ba.y; h[2][k] = ba.z; h[3][k] = ba.w;
            h[4][k] = bb.x; h[5][k] = bb.y; h[6][k] = bb.z; h[7][k] = bb.w;
        }
#pragma unroll 2
        for (int f = 0; f < CINF; ++f) {
            float4 wa = *(const float4*)&W1[f * CHID + c0];
            float4 wb = *(const float4*)&W1[f * CHID + c0 + 4];
#pragma unroll
            for (int k = 0; k < 4; ++k) {
                float s = sfeat[(k0 + k) * CINF + f];
                h[0][k] = fmaf(s, wa.x, h[0][k]);
                h[1][k] = fmaf(s, wa.y, h[1][k]);
                h[2][k] = fmaf(s, wa.z, h[2][k]);
                h[3][k] = fmaf(s, wa.w, h[3][k]);
                h[4][k] = fmaf(s, wb.x, h[4][k]);
                h[5][k] = fmaf(s, wb.y, h[5][k]);
                h[6][k] = fmaf(s, wb.z, h[6][k]);
                h[7][k] = fmaf(s, wb.w, h[7][k]);
            }
        }
#pragma unroll
        for (int k = 0; k < 4; ++k) {
            float4 v0, v1;
            v0.x = fmaxf(h[0][k], 0.f); v0.y = fmaxf(h[1][k], 0.f);
            v0.z = fmaxf(h[2][k], 0.f); v0.w = fmaxf(h[3][k], 0.f);
            v1.x = fmaxf(h[4][k], 0.f); v1.y = fmaxf(h[5][k], 0.f);
            v1.z = fmaxf(h[6][k], 0.f); v1.w = fmaxf(h[7][k], 0.f);
            *(float4*)&sh1[(k0 + k) * CHID + c0]     = v0;
            *(float4*)&sh1[(k0 + k) * CHID + c0 + 4] = v1;
        }
    }
    __syncthreads();

    // phase 2: acc = h1 @ W2; masked max over valid k
    float mv[8];
#pragma unroll
    for (int c = 0; c < 8; ++c) mv[c] = -FLT_MAX;
    int o0, kg;
    {
        constexpr int OG = COUT / 8;
        o0 = (t % OG) * 8;
        kg = t / OG;
        const int k0 = kg * 4;
        float a[8][4];
#pragma unroll
        for (int k = 0; k < 4; ++k) {
            a[0][k] = 0.f; a[1][k] = 0.f; a[2][k] = 0.f; a[3][k] = 0.f;
            a[4][k] = 0.f; a[5][k] = 0.f; a[6][k] = 0.f; a[7][k] = 0.f;
        }
#pragma unroll 2
        for (int cc = 0; cc < CHID; ++cc) {
            float4 wa = *(const float4*)&W2[cc * COUT + o0];
            float4 wb = *(const float4*)&W2[cc * COUT + o0 + 4];
#pragma unroll
            for (int k = 0; k < 4; ++k) {
                float s = sh1[(k0 + k) * CHID + cc];
                a[0][k] = fmaf(s, wa.x, a[0][k]);
                a[1][k] = fmaf(s, wa.y, a[1][k]);
                a[2][k] = fmaf(s, wa.z, a[2][k]);
                a[3][k] = fmaf(s, wa.w, a[3][k]);
                a[4][k] = fmaf(s, wb.x, a[4][k]);
                a[5][k] = fmaf(s, wb.y, a[5][k]);
                a[6][k] = fmaf(s, wb.z, a[6][k]);
                a[7][k] = fmaf(s, wb.w, a[7][k]);
            }
        }
#pragma unroll
        for (int k = 0; k < 4; ++k) {
            if (k0 + k < cnt) {
#pragma unroll
                for (int c = 0; c < 8; ++c) mv[c] = fmaxf(mv[c], a[c][k]);
            }
        }
    }
    __syncthreads();
    float* red = sh1;                 // [8][COUT]
#pragma unroll
    for (int c = 0; c < 8; ++c) red[kg * COUT + o0 + c] = mv[c];
    __syncthreads();
    float m = red[t];
#pragma unroll
    for (int r = 1; r < 8; ++r) m = fmaxf(m, red[r * COUT + t]);
    float res = (cnt > 0) ? fmaxf(m + b2[t], 0.f) : 0.f;
    xout[((size_t)b * N + i) * COUT + t] = res;
}

// ---------------- head ----------------
__global__ void head_kernel(const float* __restrict__ x3,
                            const float* __restrict__ Wc1, const float* __restrict__ bc1,
                            const float* __restrict__ Wc2, const float* __restrict__ bc2,
                            const float* __restrict__ Wc3, const float* __restrict__ bc3,
                            const float* __restrict__ Wd1, const float* __restrict__ bd1,
                            const float* __restrict__ Wd2, const float* __restrict__ bd2,
                            float* __restrict__ out)
{
    __shared__ float sf[256], sh[256], sh2[256], slog[40], sd[2];
    const int b = blockIdx.x, t = threadIdx.x;

    float m = -FLT_MAX;
    for (int n = 0; n < N3; ++n)
        m = fmaxf(m, x3[((size_t)b * N3 + n) * 256 + t]);
    sf[t] = m;
    __syncthreads();

    float a = bc1[t];
    for (int c = 0; c < 256; ++c) a = fmaf(sf[c], Wc1[c * 256 + t], a);
    sh[t] = fmaxf(a, 0.f);
    __syncthreads();

    a = bc2[t];
    for (int c = 0; c < 256; ++c) a = fmaf(sh[c], Wc2[c * 256 + t], a);
    sh2[t] = fmaxf(a, 0.f);
    __syncthreads();

    if (t < 40) {
        float l = bc3[t];
        for (int c = 0; c < 256; ++c) l = fmaf(sh2[c], Wc3[c * 40 + t], l);
        slog[t] = l;
    }
    float a2 = bd1[t];
    for (int c = 0; c < 256; ++c) a2 = fmaf(sf[c], Wd1[c * 256 + t], a2);
    a2 = fmaxf(a2, 0.f);
    __syncthreads();
    sh[t] = a2;
    __syncthreads();
    if (t < 2) {
        float l = bd2[t];
        for (int c = 0; c < 256; ++c) l = fmaf(sh[c], Wd2[c * 2 + t], l);
        sd[t] = l;
    }
    __syncthreads();

    if (t < 40) {
        float mx = -FLT_MAX;
        for (int j = 0; j < 40; ++j) mx = fmaxf(mx, slog[j]);
        float se = 0.f;
        for (int j = 0; j < 40; ++j) se += expf(slog[j] - mx);
        out[b * 40 + t] = slog[t] - mx - logf(se);
    }
    if (t < 2) {
        float mx = fmaxf(sd[0], sd[1]);
        float se = expf(sd[0] - mx) + expf(sd[1] - mx);
        out[NB * 40 + b * 2 + t] = sd[t] - mx - logf(se);
    }
}

// ---------------- launch ----------------
extern "C" void kernel_launch(void* const* d_in, const int* in_sizes, int n_in,
                              void* d_out, int out_size)
{
    const float* pos = (const float*)d_in[0];
    const float* W1a = (const float*)d_in[1];  const float* b1a = (const float*)d_in[2];
    const float* W1b = (const float*)d_in[3];  const float* b1b = (const float*)d_in[4];
    const float* W2a = (const float*)d_in[5];  const float* b2a = (const float*)d_in[6];
    const float* W2b = (const float*)d_in[7];  const float* b2b = (const float*)d_in[8];
    const float* W3a = (const float*)d_in[9];  const float* b3a = (const float*)d_in[10];
    const float* W3b = (const float*)d_in[11]; const float* b3b = (const float*)d_in[12];
    const float* Wc1 = (const float*)d_in[13]; const float* bc1 = (const float*)d_in[14];
    const float* Wc2 = (const float*)d_in[15]; const float* bc2 = (const float*)d_in[16];
    const float* Wc3 = (const float*)d_in[17]; const float* bc3 = (const float*)d_in[18];
    const float* Wd1 = (const float*)d_in[19]; const float* bd1 = (const float*)d_in[20];
    const float* Wd2 = (const float*)d_in[21]; const float* bd2 = (const float*)d_in[22];
    float* out = (float*)d_out;

    void *p_idx1, *p_cnt1, *p_x1, *p_fi1, *p_pos2, *p_x2g, *p_idx2, *p_cnt2,
         *p_x2, *p_fi2, *p_pos3, *p_x3g, *p_idx3, *p_cnt3, *p_x3;
    cudaGetSymbolAddress(&p_idx1, g_idx1);
    cudaGetSymbolAddress(&p_cnt1, g_cnt1);
    cudaGetSymbolAddress(&p_x1,   g_x1);
    cudaGetSymbolAddress(&p_fi1,  g_fi1);
    cudaGetSymbolAddress(&p_pos2, g_pos2);
    cudaGetSymbolAddress(&p_x2g,  g_x2g);
    cudaGetSymbolAddress(&p_idx2, g_idx2);
    cudaGetSymbolAddress(&p_cnt2, g_cnt2);
    cudaGetSymbolAddress(&p_x2,   g_x2);
    cudaGetSymbolAddress(&p_fi2,  g_fi2);
    cudaGetSymbolAddress(&p_pos3, g_pos3);
    cudaGetSymbolAddress(&p_x3g,  g_x3g);
    cudaGetSymbolAddress(&p_idx3, g_idx3);
    cudaGetSymbolAddress(&p_cnt3, g_cnt3);
    cudaGetSymbolAddress(&p_x3,   g_x3);

    const int smMega1 = N1 * 12 + 128;            // 49280 (fps spos + reduce)
    const int smMega2 = N2 * 12 + 128;            // 24704
    const int smKnn3  = 256 * 16;                 // 4096
    const int sh1b = (32 * 3   + 32 * 64)  * 4;
    const int sh2b = (32 * 67  + 32 * 128) * 4;
    const int sh3b = (32 * 131 + 32 * 256) * 4;   // 49536
    cudaFuncSetAttribute(mega_kernel<16>,
                         cudaFuncAttributeMaxDynamicSharedMemorySize, 50176);
    cudaFuncSetAttribute(conv_kernel<128, 256, 256>,
                         cudaFuncAttributeMaxDynamicSharedMemorySize, 50176);

    const float r1 = 0.2f, r2 = 0.4f, r3 = 1.0f;

    // level 1: knn1 + fps1 fused (both read pos only)
    mega_kernel<16><<<NB + (N1 / 256) * NB, 256, smMega1>>>(
        pos, r1 * r1, (int*)p_idx1, (int*)p_cnt1, N2, (int*)p_fi1);
    conv_kernel<0, 64, 64><<<dim3(N1, NB), 64, sh1b>>>(
        nullptr, pos, (int*)p_idx1, (int*)p_cnt1,
        W1a, b1a, W1b, b1b, (float*)p_x1, N1);
    gather_kernel<<<256, 256>>>((float*)p_x1, pos, (int*)p_fi1,
                                (float*)p_x2g, (float*)p_pos2, N1, N2, 64);

    // level 2: knn2 + fps2 fused
    mega_kernel<8><<<NB + (N2 / 256) * NB, 256, smMega2>>>(
        (float*)p_pos2, r2 * r2, (int*)p_idx2, (int*)p_cnt2, N3, (int*)p_fi2);
    conv_kernel<64, 128, 128><<<dim3(N2, NB), 128, sh2b>>>(
        (float*)p_x2g, (float*)p_pos2, (int*)p_idx2, (int*)p_cnt2,
        W2a, b2a, W2b, b2b, (float*)p_x2, N2);
    gather_kernel<<<256, 256>>>((float*)p_x2, (float*)p_pos2, (int*)p_fi2,
                                (float*)p_x3g, (float*)p_pos3, N2, N3, 128);

    // level 3
    knn_kernel<<<(N3 / 256) * NB, 256, smKnn3>>>(
        (float*)p_pos3, N3, r3 * r3, (int*)p_idx3, (int*)p_cnt3);
    conv_kernel<128, 256, 256><<<dim3(N3, NB), 256, sh3b>>>(
        (float*)p_x3g, (float*)p_pos3, (int*)p_idx3, (int*)p_cnt3,
        W3a, b3a, W3b, b3b, (float*)p_x3, N3);

    // head
    head_kernel<<<NB, 256>>>((float*)p_x3, Wc1, bc1, Wc2, bc2, Wc3, bc3,
                             Wd1, bd1, Wd2, bd2, out);

    (void)in_sizes; (void)n_in; (void)out_size;
}

// round 5
// speedup vs baseline: 1.9515x; 1.0644x over previous
#include <cuda_runtime.h>
#include <math.h>
#include <float.h>

typedef unsigned int u32;

static constexpr int NB = 8, N1 = 4096, N2 = 2048, N3 = 512, KNN = 32;

// ---------------- scratch ----------------
__device__ int   g_idx1[NB * N1 * KNN];
__device__ int   g_cnt1[NB * N1];
__device__ float g_a1  [NB * N1 * 64];
__device__ float g_x1  [NB * N1 * 64];
__device__ int   g_fi1 [NB * N2];
__device__ float g_pos2[NB * N2 * 3];
__device__ float g_x2g [NB * N2 * 64];
__device__ float g_a2  [NB * N2 * 128];
__device__ int   g_idx2[NB * N2 * KNN];
__device__ int   g_cnt2[NB * N2];
__device__ float g_x2  [NB * N2 * 128];
__device__ int   g_fi2 [NB * N3];
__device__ float g_pos3[NB * N3 * 3];
__device__ float g_x3g [NB * N3 * 128];
__device__ float g_a3  [NB * N3 * 256];
__device__ int   g_idx3[NB * N3 * KNN];
__device__ int   g_cnt3[NB * N3];
__device__ float g_x3  [NB * N3 * 256];

// ---------------- per-node a_j = [x_j, pos_j] @ W1 + b1 ----------------
template <int CINX, int CHID>
__global__ void __launch_bounds__(256)
node_pre_kernel(const float* __restrict__ x, const float* __restrict__ pos,
                const float* __restrict__ W1, const float* __restrict__ b1,
                float* __restrict__ a, int nNodes)
{
    int tid = blockIdx.x * 256 + threadIdx.x;
    if (tid >= nNodes * CHID) return;
    int node = tid / CHID, c = tid - node * CHID;
    float acc = b1[c];
    if (CINX > 0) {
        const float* xr = x + (size_t)node * CINX;
#pragma unroll 4
        for (int f = 0; f < CINX; ++f)
            acc = fmaf(xr[f], W1[f * CHID + c], acc);
    }
    const float* pr = pos + (size_t)node * 3;
    acc = fmaf(pr[0], W1[(CINX + 0) * CHID + c], acc);
    acc = fmaf(pr[1], W1[(CINX + 1) * CHID + c], acc);
    acc = fmaf(pr[2], W1[(CINX + 2) * CHID + c], acc);
    a[tid] = acc;
}

// ---------------- KNN device routine (256 threads/block) ----------------
__device__ void knn_dev(const float* __restrict__ pb, int N, float r2v,
                        int* __restrict__ oidx, int* __restrict__ ocnt,
                        int qb, float4* sj)
{
    const int t = threadIdx.x;
    const int i = qb * 256 + t;
    const float xi = pb[i * 3 + 0], yi = pb[i * 3 + 1], zi = pb[i * 3 + 2];
    const float sqi = __fadd_rn(__fadd_rn(__fmul_rn(xi, xi), __fmul_rn(yi, yi)),
                                __fmul_rn(zi, zi));
    const float m2x = -2.f * xi, m2y = -2.f * yi, m2z = -2.f * zi;

    float bd[KNN];
    int   bi_[KNN];
#pragma unroll
    for (int k = 0; k < KNN; ++k) { bd[k] = FLT_MAX; bi_[k] = 0; }
    float worst = FLT_MAX;

    for (int t0 = 0; t0 < N; t0 += 256) {
        __syncthreads();
        {
            int j = t0 + t;
            float x = pb[j * 3 + 0], y = pb[j * 3 + 1], z = pb[j * 3 + 2];
            float sq = __fadd_rn(__fadd_rn(__fmul_rn(x, x), __fmul_rn(y, y)),
                                 __fmul_rn(z, z));
            sj[t] = make_float4(x, y, z, sq);
        }
        __syncthreads();
#pragma unroll 4
        for (int jj = 0; jj < 256; ++jj) {
            float4 q = sj[jj];
            float d2 = sqi + fmaf(m2x, q.x, fmaf(m2y, q.y, fmaf(m2z, q.z, q.w)));
            int j = t0 + jj;
            if (d2 <= r2v && d2 < worst && j != i) {
                int p = KNN - 1;
                while (p > 0 && bd[p - 1] > d2) {
                    bd[p] = bd[p - 1]; bi_[p] = bi_[p - 1]; --p;
                }
                bd[p] = d2; bi_[p] = j;
                worst = bd[KNN - 1];
            }
        }
    }
    int cnt = 0;
    while (cnt < KNN && bd[cnt] <= r2v) ++cnt;
    ocnt[i] = cnt;
    const int base = i * KNN;
#pragma unroll
    for (int k = 0; k < KNN; ++k) oidx[base + k] = bi_[k];
}

// ---------------- FPS (256 threads): single barrier per iteration --------
template <int P>
__device__ void fps_dev(const float* __restrict__ pb, int nS,
                        int* __restrict__ out, float* sm)
{
    const int N = P * 256;
    float* spos = sm;
    u32*  svb = (u32*)(sm + N * 3);   // [2][8]
    int*  si  = (int*)(svb + 16);     // [2][8]
    const int t = threadIdx.x, w = t >> 5, l = t & 31;

    for (int e = t; e < N * 3; e += 256) spos[e] = pb[e];
    __syncthreads();

    float px[P], py[P], pz[P], mind[P];
    const float x0 = spos[0], y0 = spos[1], z0 = spos[2];
    float bv = -1.f; int bidx = 0x7fffffff;
#pragma unroll
    for (int p = 0; p < P; ++p) {
        int i = t + p * 256;
        px[p] = spos[i * 3 + 0]; py[p] = spos[i * 3 + 1]; pz[p] = spos[i * 3 + 2];
        float dx = px[p] - x0, dy = py[p] - y0, dz = pz[p] - z0;
        mind[p] = __fadd_rn(__fadd_rn(__fmul_rn(dx, dx), __fmul_rn(dy, dy)),
                            __fmul_rn(dz, dz));
        if (mind[p] > bv) { bv = mind[p]; bidx = i; }
    }
    if (t == 0) out[0] = 0;

    int par = 0;
    for (int s = 1; s < nS; ++s) {
        u32 vb = __float_as_uint(bv);                 // mind >= 0 -> monotone
        u32 m  = __reduce_max_sync(0xffffffffu, vb);
        u32 cand = (vb == m) ? (u32)bidx : 0xffffffffu;
        u32 wi = __reduce_min_sync(0xffffffffu, cand);
        if (l == 0) { svb[par * 8 + w] = m; si[par * 8 + w] = (int)wi; }
        __syncthreads();
        // every warp reduces the 8 leader values redundantly (no 2nd barrier)
        u32 v2 = (l < 8) ? svb[par * 8 + l] : 0u;
        u32 i2 = (l < 8) ? (u32)si[par * 8 + l] : 0xffffffffu;
        u32 m2 = __reduce_max_sync(0xffffffffu, v2);
        u32 c2 = (v2 == m2 && l < 8) ? i2 : 0xffffffffu;
        u32 gi = __reduce_min_sync(0xffffffffu, c2);
        if (t == 0) out[s] = (int)gi;
        const float cx = spos[gi * 3 + 0];
        const float cy = spos[gi * 3 + 1];
        const float cz = spos[gi * 3 + 2];
        par ^= 1;
        bv = -1.f; bidx = 0x7fffffff;
#pragma unroll
        for (int p = 0; p < P; ++p) {
            float dx = px[p] - cx, dy = py[p] - cy, dz = pz[p] - cz;
            float d = __fadd_rn(__fadd_rn(__fmul_rn(dx, dx), __fmul_rn(dy, dy)),
                                __fmul_rn(dz, dz));
            mind[p] = fminf(mind[p], d);
            if (mind[p] > bv) { bv = mind[p]; bidx = t + p * 256; }
        }
    }
}

// ---------------- fused KNN + FPS launch ----------------
template <int P>
__global__ void __launch_bounds__(256)
mega_kernel(const float* __restrict__ pos, float r2v,
            int* __restrict__ oidx, int* __restrict__ ocnt,
            int nS, int* __restrict__ fi)
{
    extern __shared__ char sm[];
    const int N = P * 256;
    if (blockIdx.x < NB) {
        fps_dev<P>(pos + (size_t)blockIdx.x * N * 3, nS,
                   fi + blockIdx.x * nS, (float*)sm);
    } else {
        int kb = blockIdx.x - NB;
        int b = kb % NB, qb = kb / NB;
        knn_dev(pos + (size_t)b * N * 3, N, r2v,
                oidx + (size_t)b * N * KNN, ocnt + b * N, qb, (float4*)sm);
    }
}

__global__ void __launch_bounds__(256)
knn_kernel(const float* __restrict__ pos, int N, float r2v,
           int* __restrict__ oidx, int* __restrict__ ocnt)
{
    extern __shared__ char sm[];
    int b = blockIdx.x % NB, qb = blockIdx.x / NB;
    knn_dev(pos + (size_t)b * N * 3, N, r2v,
            oidx + (size_t)b * N * KNN, ocnt + b * N, qb, (float4*)sm);
}

// ---------------- gather after FPS ----------------
__global__ void gather_kernel(const float* __restrict__ xin,
                              const float* __restrict__ posin,
                              const int* __restrict__ fi,
                              float* __restrict__ xo, float* __restrict__ poso,
                              int Nin, int Nout, int C)
{
    const int tid = blockIdx.x * blockDim.x + threadIdx.x;
    const int stride = gridDim.x * blockDim.x;
    const int totX = NB * Nout * C;
    for (int e = tid; e < totX; e += stride) {
        int c = e % C, m = (e / C) % Nout, b = e / (C * Nout);
        int j = fi[b * Nout + m];
        xo[e] = xin[((size_t)b * Nin + j) * C + c];
    }
    const int totP = NB * Nout * 3;
    for (int e = tid; e < totP; e += stride) {
        int d = e % 3, m = (e / 3) % Nout, b = e / (3 * Nout);
        int j = fi[b * Nout + m];
        poso[e] = posin[((size_t)b * Nin + j) * 3 + d];
    }
}

// ---------------- PointNetConv (decomposed): h = relu(a_j - c_i) @ W2 ----
template <int CHID, int COUT>
__global__ void __launch_bounds__(COUT)
conv_kernel(const float* __restrict__ a, const float* __restrict__ pos,
            const int* __restrict__ kidx, const int* __restrict__ kcnt,
            const float* __restrict__ W1p, const float* __restrict__ W2,
            const float* __restrict__ b2, float* __restrict__ xout, int N)
{
    constexpr int CHIDP = CHID + 4;          // padded row stride (bank-safe)
    extern __shared__ float smem[];
    float* sh1 = smem;                       // [32][CHIDP]
    float* scv = smem + 32 * CHIDP;          // [CHID]
    __shared__ int   sidx[KNN];
    __shared__ float spi[3];
    __shared__ int   scnt;

    const int b = blockIdx.y, i = blockIdx.x, t = threadIdx.x;

    if (t < KNN) sidx[t] = kidx[((size_t)b * N + i) * KNN + t];
    if (t == 0)  scnt = kcnt[b * N + i];
    if (t < 3)   spi[t] = pos[((size_t)b * N + i) * 3 + t];
    __syncthreads();
    const int cnt = scnt;
    const float p0 = spi[0], p1 = spi[1], p2 = spi[2];
    for (int c = t; c < CHID; c += COUT)
        scv[c] = fmaf(p2, W1p[2 * CHID + c],
                      fmaf(p1, W1p[CHID + c], p0 * W1p[c]));
    __syncthreads();

    // gather h = relu(a_j - c_i) for the 32 neighbors (coalesced float4)
    const float* ab = a + (size_t)b * N * CHID;
    constexpr int V = CHID / 4;
    for (int e = t; e < 32 * V; e += COUT) {
        int k = e / V, c4 = e - k * V;
        int j = sidx[k];
        float4 av = *(const float4*)&ab[(size_t)j * CHID + c4 * 4];
        float4 cv = *(const float4*)&scv[c4 * 4];
        float4 h;
        h.x = fmaxf(av.x - cv.x, 0.f);
        h.y = fmaxf(av.y - cv.y, 0.f);
        h.z = fmaxf(av.z - cv.z, 0.f);
        h.w = fmaxf(av.w - cv.w, 0.f);
        *(float4*)&sh1[k * CHIDP + c4 * 4] = h;
    }
    __syncthreads();

    // phase 2: acc = h @ W2; masked max over valid k
    float mv[8];
#pragma unroll
    for (int c = 0; c < 8; ++c) mv[c] = -FLT_MAX;
    constexpr int OG = COUT / 8;
    const int o0 = (t % OG) * 8;
    const int kg = t / OG;
    {
        const int k0 = kg * 4;
        float acc[8][4];
#pragma unroll
        for (int k = 0; k < 4; ++k) {
#pragma unroll
            for (int c = 0; c < 8; ++c) acc[c][k] = 0.f;
        }
#pragma unroll 2
        for (int cc = 0; cc < CHID; ++cc) {
            float4 wa = *(const float4*)&W2[cc * COUT + o0];
            float4 wb = *(const float4*)&W2[cc * COUT + o0 + 4];
#pragma unroll
            for (int k = 0; k < 4; ++k) {
                float s = sh1[(k0 + k) * CHIDP + cc];
                acc[0][k] = fmaf(s, wa.x, acc[0][k]);
                acc[1][k] = fmaf(s, wa.y, acc[1][k]);
                acc[2][k] = fmaf(s, wa.z, acc[2][k]);
                acc[3][k] = fmaf(s, wa.w, acc[3][k]);
                acc[4][k] = fmaf(s, wb.x, acc[4][k]);
                acc[5][k] = fmaf(s, wb.y, acc[5][k]);
                acc[6][k] = fmaf(s, wb.z, acc[6][k]);
                acc[7][k] = fmaf(s, wb.w, acc[7][k]);
            }
        }
#pragma unroll
        for (int k = 0; k < 4; ++k) {
            if (k0 + k < cnt) {
#pragma unroll
                for (int c = 0; c < 8; ++c) mv[c] = fmaxf(mv[c], acc[c][k]);
            }
        }
    }
    __syncthreads();
    float* red = sh1;                 // reuse as [8][COUT]
#pragma unroll
    for (int c = 0; c < 8; ++c) red[kg * COUT + o0 + c] = mv[c];
    __syncthreads();
    float m = red[t];
#pragma unroll
    for (int r = 1; r < 8; ++r) m = fmaxf(m, red[r * COUT + t]);
    float res = (cnt > 0) ? fmaxf(m + b2[t], 0.f) : 0.f;
    xout[((size_t)b * N + i) * COUT + t] = res;
}

// ---------------- head ----------------
__global__ void head_kernel(const float* __restrict__ x3,
                            const float* __restrict__ Wc1, const float* __restrict__ bc1,
                            const float* __restrict__ Wc2, const float* __restrict__ bc2,
                            const float* __restrict__ Wc3, const float* __restrict__ bc3,
                            const float* __restrict__ Wd1, const float* __restrict__ bd1,
                            const float* __restrict__ Wd2, const float* __restrict__ bd2,
                            float* __restrict__ out)
{
    __shared__ float sf[256], sh[256], sh2[256], slog[40], sd[2];
    const int b = blockIdx.x, t = threadIdx.x;

    float m = -FLT_MAX;
    for (int n = 0; n < N3; ++n)
        m = fmaxf(m, x3[((size_t)b * N3 + n) * 256 + t]);
    sf[t] = m;
    __syncthreads();

    float a = bc1[t];
    for (int c = 0; c < 256; ++c) a = fmaf(sf[c], Wc1[c * 256 + t], a);
    sh[t] = fmaxf(a, 0.f);
    __syncthreads();

    a = bc2[t];
    for (int c = 0; c < 256; ++c) a = fmaf(sh[c], Wc2[c * 256 + t], a);
    sh2[t] = fmaxf(a, 0.f);
    __syncthreads();

    if (t < 40) {
        float l = bc3[t];
        for (int c = 0; c < 256; ++c) l = fmaf(sh2[c], Wc3[c * 40 + t], l);
        slog[t] = l;
    }
    float a2 = bd1[t];
    for (int c = 0; c < 256; ++c) a2 = fmaf(sf[c], Wd1[c * 256 + t], a2);
    a2 = fmaxf(a2, 0.f);
    __syncthreads();
    sh[t] = a2;
    __syncthreads();
    if (t < 2) {
        float l = bd2[t];
        for (int c = 0; c < 256; ++c) l = fmaf(sh[c], Wd2[c * 2 + t], l);
        sd[t] = l;
    }
    __syncthreads();

    if (t < 40) {
        float mx = -FLT_MAX;
        for (int j = 0; j < 40; ++j) mx = fmaxf(mx, slog[j]);
        float se = 0.f;
        for (int j = 0; j < 40; ++j) se += expf(slog[j] - mx);
        out[b * 40 + t] = slog[t] - mx - logf(se);
    }
    if (t < 2) {
        float mx = fmaxf(sd[0], sd[1]);
        float se = expf(sd[0] - mx) + expf(sd[1] - mx);
        out[NB * 40 + b * 2 + t] = sd[t] - mx - logf(se);
    }
}

// ---------------- launch ----------------
extern "C" void kernel_launch(void* const* d_in, const int* in_sizes, int n_in,
                              void* d_out, int out_size)
{
    const float* pos = (const float*)d_in[0];
    const float* W1a = (const float*)d_in[1];  const float* b1a = (const float*)d_in[2];
    const float* W1b = (const float*)d_in[3];  const float* b1b = (const float*)d_in[4];
    const float* W2a = (const float*)d_in[5];  const float* b2a = (const float*)d_in[6];
    const float* W2b = (const float*)d_in[7];  const float* b2b = (const float*)d_in[8];
    const float* W3a = (const float*)d_in[9];  const float* b3a = (const float*)d_in[10];
    const float* W3b = (const float*)d_in[11]; const float* b3b = (const float*)d_in[12];
    const float* Wc1 = (const float*)d_in[13]; const float* bc1 = (const float*)d_in[14];
    const float* Wc2 = (const float*)d_in[15]; const float* bc2 = (const float*)d_in[16];
    const float* Wc3 = (const float*)d_in[17]; const float* bc3 = (const float*)d_in[18];
    const float* Wd1 = (const float*)d_in[19]; const float* bd1 = (const float*)d_in[20];
    const float* Wd2 = (const float*)d_in[21]; const float* bd2 = (const float*)d_in[22];
    float* out = (float*)d_out;

    void *p_idx1, *p_cnt1, *p_a1, *p_x1, *p_fi1, *p_pos2, *p_x2g, *p_a2,
         *p_idx2, *p_cnt2, *p_x2, *p_fi2, *p_pos3, *p_x3g, *p_a3,
         *p_idx3, *p_cnt3, *p_x3;
    cudaGetSymbolAddress(&p_idx1, g_idx1);
    cudaGetSymbolAddress(&p_cnt1, g_cnt1);
    cudaGetSymbolAddress(&p_a1,   g_a1);
    cudaGetSymbolAddress(&p_x1,   g_x1);
    cudaGetSymbolAddress(&p_fi1,  g_fi1);
    cudaGetSymbolAddress(&p_pos2, g_pos2);
    cudaGetSymbolAddress(&p_x2g,  g_x2g);
    cudaGetSymbolAddress(&p_a2,   g_a2);
    cudaGetSymbolAddress(&p_idx2, g_idx2);
    cudaGetSymbolAddress(&p_cnt2, g_cnt2);
    cudaGetSymbolAddress(&p_x2,   g_x2);
    cudaGetSymbolAddress(&p_fi2,  g_fi2);
    cudaGetSymbolAddress(&p_pos3, g_pos3);
    cudaGetSymbolAddress(&p_x3g,  g_x3g);
    cudaGetSymbolAddress(&p_a3,   g_a3);
    cudaGetSymbolAddress(&p_idx3, g_idx3);
    cudaGetSymbolAddress(&p_cnt3, g_cnt3);
    cudaGetSymbolAddress(&p_x3,   g_x3);

    const int smMega1 = N1 * 12 + 128;            // fps spos + reduce buffers
    const int smMega2 = N2 * 12 + 128;
    const int smKnn3  = 256 * 16;
    const int shc1 = (32 * (64 + 4)  + 64)  * 4;  //  8960
    const int shc2 = (32 * (128 + 4) + 128) * 4;  // 17408
    const int shc3 = (32 * (256 + 4) + 256) * 4;  // 34304
    cudaFuncSetAttribute(mega_kernel<16>,
                         cudaFuncAttributeMaxDynamicSharedMemorySize, 50176);

    const float r1 = 0.2f, r2 = 0.4f, r3 = 1.0f;

    // level 1
    node_pre_kernel<0, 64><<<(NB * N1 * 64) / 256, 256>>>(
        nullptr, pos, W1a, b1a, (float*)p_a1, NB * N1);
    mega_kernel<16><<<NB + (N1 / 256) * NB, 256, smMega1>>>(
        pos, r1 * r1, (int*)p_idx1, (int*)p_cnt1, N2, (int*)p_fi1);
    conv_kernel<64, 64><<<dim3(N1, NB), 64, shc1>>>(
        (float*)p_a1, pos, (int*)p_idx1, (int*)p_cnt1,
        W1a, W1b, b1b, (float*)p_x1, N1);
    gather_kernel<<<256, 256>>>((float*)p_x1, pos, (int*)p_fi1,
                                (float*)p_x2g, (float*)p_pos2, N1, N2, 64);

    // level 2
    node_pre_kernel<64, 128><<<(NB * N2 * 128) / 256, 256>>>(
        (float*)p_x2g, (float*)p_pos2, W2a, b2a, (float*)p_a2, NB * N2);
    mega_kernel<8><<<NB + (N2 / 256) * NB, 256, smMega2>>>(
        (float*)p_pos2, r2 * r2, (int*)p_idx2, (int*)p_cnt2, N3, (int*)p_fi2);
    conv_kernel<128, 128><<<dim3(N2, NB), 128, shc2>>>(
        (float*)p_a2, (float*)p_pos2, (int*)p_idx2, (int*)p_cnt2,
        W2a + 64 * 128, W2b, b2b, (float*)p_x2, N2);
    gather_kernel<<<256, 256>>>((float*)p_x2, (float*)p_pos2, (int*)p_fi2,
                                (float*)p_x3g, (float*)p_pos3, N2, N3, 128);

    // level 3
    node_pre_kernel<128, 256><<<(NB * N3 * 256) / 256, 256>>>(
        (float*)p_x3g, (float*)p_pos3, W3a, b3a, (float*)p_a3, NB * N3);
    knn_kernel<<<(N3 / 256) * NB, 256, smKnn3>>>(
        (float*)p_pos3, N3, r3 * r3, (int*)p_idx3, (int*)p_cnt3);
    conv_kernel<256, 256><<<dim3(N3, NB), 256, shc3>>>(
        (float*)p_a3, (float*)p_pos3, (int*)p_idx3, (int*)p_cnt3,
        W3a + 128 * 256, W3b, b3b, (float*)p_x3, N3);

    // head
    head_kernel<<<NB, 256>>>((float*)p_x3, Wc1, bc1, Wc2, bc2, Wc3, bc3,
                             Wd1, bd1, Wd2, bd2, out);

    (void)in_sizes; (void)n_in; (void)out_size;
}

// round 6
// speedup vs baseline: 5.6239x; 2.8818x over previous
#include <cuda_runtime.h>
#include <math.h>
#include <float.h>

typedef unsigned int u32;

static constexpr int NB = 8, N1 = 4096, N2 = 2048, N3 = 512, KNN = 32;

// ---------------- scratch ----------------
__device__ int   g_idx1[NB * N1 * KNN];
__device__ int   g_cnt1[NB * N1];
__device__ float g_a1  [NB * N1 * 64];
__device__ float g_x1  [NB * N1 * 64];
__device__ int   g_fi1 [NB * N2];
__device__ float g_pos2[NB * N2 * 3];
__device__ float g_x2g [NB * N2 * 64];
__device__ float g_a2  [NB * N2 * 128];
__device__ int   g_idx2[NB * N2 * KNN];
__device__ int   g_cnt2[NB * N2];
__device__ float g_x2  [NB * N2 * 128];
__device__ int   g_fi2 [NB * N3];
__device__ float g_pos3[NB * N3 * 3];
__device__ float g_x3g [NB * N3 * 128];
__device__ float g_a3  [NB * N3 * 256];
__device__ int   g_idx3[NB * N3 * KNN];
__device__ int   g_cnt3[NB * N3];
__device__ float g_x3  [NB * N3 * 256];

// ---------------- per-node a_j = [x_j, pos_j] @ W1 + b1 ----------------
template <int CINX, int CHID>
__global__ void __launch_bounds__(256)
node_pre_kernel(const float* __restrict__ x, const float* __restrict__ pos,
                const float* __restrict__ W1, const float* __restrict__ b1,
                float* __restrict__ a, int nNodes)
{
    int tid = blockIdx.x * 256 + threadIdx.x;
    if (tid >= nNodes * CHID) return;
    int node = tid / CHID, c = tid - node * CHID;
    float acc = b1[c];
    if (CINX > 0) {
        const float* xr = x + (size_t)node * CINX;
#pragma unroll 4
        for (int f = 0; f < CINX; ++f)
            acc = fmaf(xr[f], W1[f * CHID + c], acc);
    }
    const float* pr = pos + (size_t)node * 3;
    acc = fmaf(pr[0], W1[(CINX + 0) * CHID + c], acc);
    acc = fmaf(pr[1], W1[(CINX + 1) * CHID + c], acc);
    acc = fmaf(pr[2], W1[(CINX + 2) * CHID + c], acc);
    a[tid] = acc;
}

// ---------------- KNN: register-resident branch-free top-32 ----------------
// Sorted ascending; all list indices compile-time so bd/bi live in registers.
// Insert is a fully unrolled predicated compare/shift: no local memory, no
// serial dependence chain. Strict compares + ascending-j scan keep the
// lowest index first among ties, matching lax.top_k.
__device__ void knn_dev(const float* __restrict__ pb, int N, float r2v,
                        int* __restrict__ oidx, int* __restrict__ ocnt,
                        int qb, float4* sj)
{
    const int t = threadIdx.x;
    const int i = qb * 256 + t;
    const float xi = pb[i * 3 + 0], yi = pb[i * 3 + 1], zi = pb[i * 3 + 2];
    const float sqi = __fadd_rn(__fadd_rn(__fmul_rn(xi, xi), __fmul_rn(yi, yi)),
                                __fmul_rn(zi, zi));
    const float m2x = -2.f * xi, m2y = -2.f * yi, m2z = -2.f * zi;

    float bd[KNN];
    int   bi_[KNN];
#pragma unroll
    for (int k = 0; k < KNN; ++k) { bd[k] = FLT_MAX; bi_[k] = 0; }
    float worst = FLT_MAX;

    for (int t0 = 0; t0 < N; t0 += 256) {
        __syncthreads();
        {
            int j = t0 + t;
            float x = pb[j * 3 + 0], y = pb[j * 3 + 1], z = pb[j * 3 + 2];
            float sq = __fadd_rn(__fadd_rn(__fmul_rn(x, x), __fmul_rn(y, y)),
                                 __fmul_rn(z, z));
            sj[t] = make_float4(x, y, z, sq);
        }
        __syncthreads();
#pragma unroll 2
        for (int jj = 0; jj < 256; ++jj) {
            float4 q = sj[jj];
            float d2 = sqi + fmaf(m2x, q.x, fmaf(m2y, q.y, fmaf(m2z, q.z, q.w)));
            int j = t0 + jj;
            if (d2 <= r2v && d2 < worst && j != i) {
#pragma unroll
                for (int k = KNN - 1; k > 0; --k) {
                    if (bd[k - 1] > d2)      { bd[k] = bd[k - 1]; bi_[k] = bi_[k - 1]; }
                    else if (bd[k] > d2)     { bd[k] = d2;        bi_[k] = j; }
                }
                if (bd[0] > d2)              { bd[0] = d2;        bi_[0] = j; }
                worst = bd[KNN - 1];
            }
        }
    }
    int cnt = 0;
#pragma unroll
    for (int k = 0; k < KNN; ++k) cnt += (bd[k] <= r2v) ? 1 : 0;
    ocnt[i] = cnt;
    const int base = i * KNN;
#pragma unroll
    for (int k = 0; k < KNN; ++k) oidx[base + k] = bi_[k];
}

// ---------------- FPS (256 threads): single barrier per iteration --------
template <int P>
__device__ void fps_dev(const float* __restrict__ pb, int nS,
                        int* __restrict__ out, float* sm)
{
    const int N = P * 256;
    float* spos = sm;
    u32*  svb = (u32*)(sm + N * 3);   // [2][8]
    int*  si  = (int*)(svb + 16);     // [2][8]
    const int t = threadIdx.x, w = t >> 5, l = t & 31;

    for (int e = t; e < N * 3; e += 256) spos[e] = pb[e];
    __syncthreads();

    float px[P], py[P], pz[P], mind[P];
    const float x0 = spos[0], y0 = spos[1], z0 = spos[2];
    float bv = -1.f; int bidx = 0x7fffffff;
#pragma unroll
    for (int p = 0; p < P; ++p) {
        int i = t + p * 256;
        px[p] = spos[i * 3 + 0]; py[p] = spos[i * 3 + 1]; pz[p] = spos[i * 3 + 2];
        float dx = px[p] - x0, dy = py[p] - y0, dz = pz[p] - z0;
        mind[p] = __fadd_rn(__fadd_rn(__fmul_rn(dx, dx), __fmul_rn(dy, dy)),
                            __fmul_rn(dz, dz));
        if (mind[p] > bv) { bv = mind[p]; bidx = i; }
    }
    if (t == 0) out[0] = 0;

    int par = 0;
    for (int s = 1; s < nS; ++s) {
        u32 vb = __float_as_uint(bv);                 // mind >= 0 -> monotone
        u32 m  = __reduce_max_sync(0xffffffffu, vb);
        u32 cand = (vb == m) ? (u32)bidx : 0xffffffffu;
        u32 wi = __reduce_min_sync(0xffffffffu, cand);
        if (l == 0) { svb[par * 8 + w] = m; si[par * 8 + w] = (int)wi; }
        __syncthreads();
        u32 v2 = (l < 8) ? svb[par * 8 + l] : 0u;
        u32 i2 = (l < 8) ? (u32)si[par * 8 + l] : 0xffffffffu;
        u32 m2 = __reduce_max_sync(0xffffffffu, v2);
        u32 c2 = (v2 == m2 && l < 8) ? i2 : 0xffffffffu;
        u32 gi = __reduce_min_sync(0xffffffffu, c2);
        if (t == 0) out[s] = (int)gi;
        const float cx = spos[gi * 3 + 0];
        const float cy = spos[gi * 3 + 1];
        const float cz = spos[gi * 3 + 2];
        par ^= 1;
        bv = -1.f; bidx = 0x7fffffff;
#pragma unroll
        for (int p = 0; p < P; ++p) {
            float dx = px[p] - cx, dy = py[p] - cy, dz = pz[p] - cz;
            float d = __fadd_rn(__fadd_rn(__fmul_rn(dx, dx), __fmul_rn(dy, dy)),
                                __fmul_rn(dz, dz));
            mind[p] = fminf(mind[p], d);
            if (mind[p] > bv) { bv = mind[p]; bidx = t + p * 256; }
        }
    }
}

// ---------------- fused KNN + FPS launch (1 block/SM allowed) ----------
template <int P>
__global__ void __launch_bounds__(256, 1)
mega_kernel(const float* __restrict__ pos, float r2v,
            int* __restrict__ oidx, int* __restrict__ ocnt,
            int nS, int* __restrict__ fi)
{
    extern __shared__ char sm[];
    const int N = P * 256;
    if (blockIdx.x < NB) {
        fps_dev<P>(pos + (size_t)blockIdx.x * N * 3, nS,
                   fi + blockIdx.x * nS, (float*)sm);
    } else {
        int kb = blockIdx.x - NB;
        int b = kb % NB, qb = kb / NB;
        knn_dev(pos + (size_t)b * N * 3, N, r2v,
                oidx + (size_t)b * N * KNN, ocnt + b * N, qb, (float4*)sm);
    }
}

__global__ void __launch_bounds__(256, 1)
knn_kernel(const float* __restrict__ pos, int N, float r2v,
           int* __restrict__ oidx, int* __restrict__ ocnt)
{
    extern __shared__ char sm[];
    int b = blockIdx.x % NB, qb = blockIdx.x / NB;
    knn_dev(pos + (size_t)b * N * 3, N, r2v,
            oidx + (size_t)b * N * KNN, ocnt + b * N, qb, (float4*)sm);
}

// ---------------- gather after FPS ----------------
__global__ void gather_kernel(const float* __restrict__ xin,
                              const float* __restrict__ posin,
                              const int* __restrict__ fi,
                              float* __restrict__ xo, float* __restrict__ poso,
                              int Nin, int Nout, int C)
{
    const int tid = blockIdx.x * blockDim.x + threadIdx.x;
    const int stride = gridDim.x * blockDim.x;
    const int totX = NB * Nout * C;
    for (int e = tid; e < totX; e += stride) {
        int c = e % C, m = (e / C) % Nout, b = e / (C * Nout);
        int j = fi[b * Nout + m];
        xo[e] = xin[((size_t)b * Nin + j) * C + c];
    }
    const int totP = NB * Nout * 3;
    for (int e = tid; e < totP; e += stride) {
        int d = e % 3, m = (e / 3) % Nout, b = e / (3 * Nout);
        int j = fi[b * Nout + m];
        poso[e] = posin[((size_t)b * Nin + j) * 3 + d];
    }
}

// ---------------- PointNetConv (decomposed), TP points per 256-thr block --
template <int CHID, int COUT, int TP>
__global__ void __launch_bounds__(COUT * TP)
conv_kernel(const float* __restrict__ a, const float* __restrict__ pos,
            const int* __restrict__ kidx, const int* __restrict__ kcnt,
            const float* __restrict__ W1p, const float* __restrict__ W2,
            const float* __restrict__ b2, float* __restrict__ xout, int N)
{
    constexpr int CHIDP = CHID + 4;              // padded (bank-safe)
    constexpr int GSZ = 32 * CHIDP + CHID;       // floats per group
    extern __shared__ float smem[];
    const int tg = threadIdx.x / COUT;           // group -> point
    const int t  = threadIdx.x % COUT;
    float* sh1 = smem + tg * GSZ;                // [32][CHIDP]
    float* scv = sh1 + 32 * CHIDP;               // [CHID]
    __shared__ int   sidx[TP][KNN];
    __shared__ float spi[TP][3];
    __shared__ int   scnt[TP];

    const int b = blockIdx.y;
    const int i = blockIdx.x * TP + tg;

    if (t < KNN) sidx[tg][t] = kidx[((size_t)b * N + i) * KNN + t];
    if (t == 0)  scnt[tg] = kcnt[b * N + i];
    if (t < 3)   spi[tg][t] = pos[((size_t)b * N + i) * 3 + t];
    __syncthreads();
    const int cnt = scnt[tg];
    const float p0 = spi[tg][0], p1 = spi[tg][1], p2 = spi[tg][2];
    for (int c = t; c < CHID; c += COUT)
        scv[c] = fmaf(p2, W1p[2 * CHID + c],
                      fmaf(p1, W1p[CHID + c], p0 * W1p[c]));
    __syncthreads();

    // gather h = relu(a_j - c_i) for 32 neighbor slots (coalesced float4)
    const float* ab = a + (size_t)b * N * CHID;
    constexpr int V = CHID / 4;
    for (int e = t; e < 32 * V; e += COUT) {
        int k = e / V, c4 = e - k * V;
        int j = sidx[tg][k];
        float4 av = *(const float4*)&ab[(size_t)j * CHID + c4 * 4];
        float4 cv = *(const float4*)&scv[c4 * 4];
        float4 h;
        h.x = fmaxf(av.x - cv.x, 0.f);
        h.y = fmaxf(av.y - cv.y, 0.f);
        h.z = fmaxf(av.z - cv.z, 0.f);
        h.w = fmaxf(av.w - cv.w, 0.f);
        *(float4*)&sh1[k * CHIDP + c4 * 4] = h;
    }
    __syncthreads();

    // phase 2: acc = h @ W2; masked max over valid k
    float mv[8];
#pragma unroll
    for (int c = 0; c < 8; ++c) mv[c] = -FLT_MAX;
    constexpr int OG = COUT / 8;
    const int o0 = (t % OG) * 8;
    const int kg = t / OG;
    {
        const int k0 = kg * 4;
        float acc[8][4];
#pragma unroll
        for (int k = 0; k < 4; ++k) {
#pragma unroll
            for (int c = 0; c < 8; ++c) acc[c][k] = 0.f;
        }
#pragma unroll 2
        for (int cc = 0; cc < CHID; ++cc) {
            float4 wa = *(const float4*)&W2[cc * COUT + o0];
            float4 wb = *(const float4*)&W2[cc * COUT + o0 + 4];
#pragma unroll
            for (int k = 0; k < 4; ++k) {
                float s = sh1[(k0 + k) * CHIDP + cc];
                acc[0][k] = fmaf(s, wa.x, acc[0][k]);
                acc[1][k] = fmaf(s, wa.y, acc[1][k]);
                acc[2][k] = fmaf(s, wa.z, acc[2][k]);
                acc[3][k] = fmaf(s, wa.w, acc[3][k]);
                acc[4][k] = fmaf(s, wb.x, acc[4][k]);
                acc[5][k] = fmaf(s, wb.y, acc[5][k]);
                acc[6][k] = fmaf(s, wb.z, acc[6][k]);
                acc[7][k] = fmaf(s, wb.w, acc[7][k]);
            }
        }
#pragma unroll
        for (int k = 0; k < 4; ++k) {
            if (k0 + k < cnt) {
#pragma unroll
                for (int c = 0; c < 8; ++c) mv[c] = fmaxf(mv[c], acc[c][k]);
            }
        }
    }
    __syncthreads();
    float* red = sh1;                 // group-local reuse as [8][COUT]
#pragma unroll
    for (int c = 0; c < 8; ++c) red[kg * COUT + o0 + c] = mv[c];
    __syncthreads();
    float m = red[t];
#pragma unroll
    for (int r = 1; r < 8; ++r) m = fmaxf(m, red[r * COUT + t]);
    float res = (cnt > 0) ? fmaxf(m + b2[t], 0.f) : 0.f;
    xout[((size_t)b * N + i) * COUT + t] = res;
}

// ---------------- head ----------------
__global__ void head_kernel(const float* __restrict__ x3,
                            const float* __restrict__ Wc1, const float* __restrict__ bc1,
                            const float* __restrict__ Wc2, const float* __restrict__ bc2,
                            const float* __restrict__ Wc3, const float* __restrict__ bc3,
                            const float* __restrict__ Wd1, const float* __restrict__ bd1,
                            const float* __restrict__ Wd2, const float* __restrict__ bd2,
                            float* __restrict__ out)
{
    __shared__ float sf[256], sh[256], sh2[256], slog[40], sd[2];
    const int b = blockIdx.x, t = threadIdx.x;

    float m = -FLT_MAX;
    for (int n = 0; n < N3; ++n)
        m = fmaxf(m, x3[((size_t)b * N3 + n) * 256 + t]);
    sf[t] = m;
    __syncthreads();

    float a = bc1[t];
    for (int c = 0; c < 256; ++c) a = fmaf(sf[c], Wc1[c * 256 + t], a);
    sh[t] = fmaxf(a, 0.f);
    __syncthreads();

    a = bc2[t];
    for (int c = 0; c < 256; ++c) a = fmaf(sh[c], Wc2[c * 256 + t], a);
    sh2[t] = fmaxf(a, 0.f);
    __syncthreads();

    if (t < 40) {
        float l = bc3[t];
        for (int c = 0; c < 256; ++c) l = fmaf(sh2[c], Wc3[c * 40 + t], l);
        slog[t] = l;
    }
    float a2 = bd1[t];
    for (int c = 0; c < 256; ++c) a2 = fmaf(sf[c], Wd1[c * 256 + t], a2);
    a2 = fmaxf(a2, 0.f);
    __syncthreads();
    sh[t] = a2;
    __syncthreads();
    if (t < 2) {
        float l = bd2[t];
        for (int c = 0; c < 256; ++c) l = fmaf(sh[c], Wd2[c * 2 + t], l);
        sd[t] = l;
    }
    __syncthreads();

    if (t < 40) {
        float mx = -FLT_MAX;
        for (int j = 0; j < 40; ++j) mx = fmaxf(mx, slog[j]);
        float se = 0.f;
        for (int j = 0; j < 40; ++j) se += expf(slog[j] - mx);
        out[b * 40 + t] = slog[t] - mx - logf(se);
    }
    if (t < 2) {
        float mx = fmaxf(sd[0], sd[1]);
        float se = expf(sd[0] - mx) + expf(sd[1] - mx);
        out[NB * 40 + b * 2 + t] = sd[t] - mx - logf(se);
    }
}

// ---------------- launch ----------------
extern "C" void kernel_launch(void* const* d_in, const int* in_sizes, int n_in,
                              void* d_out, int out_size)
{
    const float* pos = (const float*)d_in[0];
    const float* W1a = (const float*)d_in[1];  const float* b1a = (const float*)d_in[2];
    const float* W1b = (const float*)d_in[3];  const float* b1b = (const float*)d_in[4];
    const float* W2a = (const float*)d_in[5];  const float* b2a = (const float*)d_in[6];
    const float* W2b = (const float*)d_in[7];  const float* b2b = (const float*)d_in[8];
    const float* W3a = (const float*)d_in[9];  const float* b3a = (const float*)d_in[10];
    const float* W3b = (const float*)d_in[11]; const float* b3b = (const float*)d_in[12];
    const float* Wc1 = (const float*)d_in[13]; const float* bc1 = (const float*)d_in[14];
    const float* Wc2 = (const float*)d_in[15]; const float* bc2 = (const float*)d_in[16];
    const float* Wc3 = (const float*)d_in[17]; const float* bc3 = (const float*)d_in[18];
    const float* Wd1 = (const float*)d_in[19]; const float* bd1 = (const float*)d_in[20];
    const float* Wd2 = (const float*)d_in[21]; const float* bd2 = (const float*)d_in[22];
    float* out = (float*)d_out;

    void *p_idx1, *p_cnt1, *p_a1, *p_x1, *p_fi1, *p_pos2, *p_x2g, *p_a2,
         *p_idx2, *p_cnt2, *p_x2, *p_fi2, *p_pos3, *p_x3g, *p_a3,
         *p_idx3, *p_cnt3, *p_x3;
    cudaGetSymbolAddress(&p_idx1, g_idx1);
    cudaGetSymbolAddress(&p_cnt1, g_cnt1);
    cudaGetSymbolAddress(&p_a1,   g_a1);
    cudaGetSymbolAddress(&p_x1,   g_x1);
    cudaGetSymbolAddress(&p_fi1,  g_fi1);
    cudaGetSymbolAddress(&p_pos2, g_pos2);
    cudaGetSymbolAddress(&p_x2g,  g_x2g);
    cudaGetSymbolAddress(&p_a2,   g_a2);
    cudaGetSymbolAddress(&p_idx2, g_idx2);
    cudaGetSymbolAddress(&p_cnt2, g_cnt2);
    cudaGetSymbolAddress(&p_x2,   g_x2);
    cudaGetSymbolAddress(&p_fi2,  g_fi2);
    cudaGetSymbolAddress(&p_pos3, g_pos3);
    cudaGetSymbolAddress(&p_x3g,  g_x3g);
    cudaGetSymbolAddress(&p_a3,   g_a3);
    cudaGetSymbolAddress(&p_idx3, g_idx3);
    cudaGetSymbolAddress(&p_cnt3, g_cnt3);
    cudaGetSymbolAddress(&p_x3,   g_x3);

    const int smMega1 = N1 * 12 + 128;
    const int smMega2 = N2 * 12 + 128;
    const int smKnn3  = 256 * 16;
    const int shc1 = 4 * (32 * (64 + 4)  + 64)  * 4;   // 35840
    const int shc2 = 2 * (32 * (128 + 4) + 128) * 4;   // 34816
    const int shc3 = 1 * (32 * (256 + 4) + 256) * 4;   // 34304
    cudaFuncSetAttribute(mega_kernel<16>,
                         cudaFuncAttributeMaxDynamicSharedMemorySize, 50176);

    const float r1 = 0.2f, r2 = 0.4f, r3 = 1.0f;

    // level 1
    node_pre_kernel<0, 64><<<(NB * N1 * 64) / 256, 256>>>(
        nullptr, pos, W1a, b1a, (float*)p_a1, NB * N1);
    mega_kernel<16><<<NB + (N1 / 256) * NB, 256, smMega1>>>(
        pos, r1 * r1, (int*)p_idx1, (int*)p_cnt1, N2, (int*)p_fi1);
    conv_kernel<64, 64, 4><<<dim3(N1 / 4, NB), 256, shc1>>>(
        (float*)p_a1, pos, (int*)p_idx1, (int*)p_cnt1,
        W1a, W1b, b1b, (float*)p_x1, N1);
    gather_kernel<<<256, 256>>>((float*)p_x1, pos, (int*)p_fi1,
                                (float*)p_x2g, (float*)p_pos2, N1, N2, 64);

    // level 2
    node_pre_kernel<64, 128><<<(NB * N2 * 128) / 256, 256>>>(
        (float*)p_x2g, (float*)p_pos2, W2a, b2a, (float*)p_a2, NB * N2);
    mega_kernel<8><<<NB + (N2 / 256) * NB, 256, smMega2>>>(
        (float*)p_pos2, r2 * r2, (int*)p_idx2, (int*)p_cnt2, N3, (int*)p_fi2);
    conv_kernel<128, 128, 2><<<dim3(N2 / 2, NB), 256, shc2>>>(
        (float*)p_a2, (float*)p_pos2, (int*)p_idx2, (int*)p_cnt2,
        W2a + 64 * 128, W2b, b2b, (float*)p_x2, N2);
    gather_kernel<<<256, 256>>>((float*)p_x2, (float*)p_pos2, (int*)p_fi2,
                                (float*)p_x3g, (float*)p_pos3, N2, N3, 128);

    // level 3
    node_pre_kernel<128, 256><<<(NB * N3 * 256) / 256, 256>>>(
        (float*)p_x3g, (float*)p_pos3, W3a, b3a, (float*)p_a3, NB * N3);
    knn_kernel<<<(N3 / 256) * NB, 256, smKnn3>>>(
        (float*)p_pos3, N3, r3 * r3, (int*)p_idx3, (int*)p_cnt3);
    conv_kernel<256, 256, 1><<<dim3(N3, NB), 256, shc3>>>(
        (float*)p_a3, (float*)p_pos3, (int*)p_idx3, (int*)p_cnt3,
        W3a + 128 * 256, W3b, b3b, (float*)p_x3, N3);

    // head
    head_kernel<<<NB, 256>>>((float*)p_x3, Wc1, bc1, Wc2, bc2, Wc3, bc3,
                             Wd1, bd1, Wd2, bd2, out);

    (void)in_sizes; (void)n_in; (void)out_size;
}